// round 1
// baseline (speedup 1.0000x reference)
#include <cuda_runtime.h>

#define P_RAYS 262144
#define NSTEP 64
#define NIMP 32
#define BS 64
#define RBLK 256
#define RGRID 256

// Deterministic reduction scratch (device globals: no allocation)
__device__ float g_part0[RGRID];
__device__ float g_part1[RGRID];
__device__ int   g_cntp[RGRID];
__device__ float g_mean0;
__device__ float g_mean1;

// Pass 1: per-block partial sums of si over masked rays (deterministic tree)
__global__ void k_reduce1(const float* __restrict__ rd, const float* __restrict__ cam) {
    __shared__ float s0[RBLK], s1[RBLK];
    __shared__ int   sc[RBLK];
    int tid = threadIdx.x;
    float cx = cam[0], cy = cam[1], cz = cam[2];
    float cc = cx * cx + cy * cy + cz * cz;
    float acc0 = 0.f, acc1 = 0.f;
    int cnt = 0;
    for (int r = blockIdx.x * RBLK + tid; r < P_RAYS; r += RBLK * RGRID) {
        float dx = rd[3 * r + 0], dy = rd[3 * r + 1], dz = rd[3 * r + 2];
        float dot = dx * cx + dy * cy + dz * cz;
        float under = dot * dot - (cc - 1.0f);
        if (under > 0.0f) {
            float sq = sqrtf(under);
            acc0 += (-sq - dot);
            acc1 += ( sq - dot);
            cnt++;
        }
    }
    s0[tid] = acc0; s1[tid] = acc1; sc[tid] = cnt;
    __syncthreads();
    for (int s = RBLK / 2; s > 0; s >>= 1) {
        if (tid < s) { s0[tid] += s0[tid + s]; s1[tid] += s1[tid + s]; sc[tid] += sc[tid + s]; }
        __syncthreads();
    }
    if (tid == 0) { g_part0[blockIdx.x] = s0[0]; g_part1[blockIdx.x] = s1[0]; g_cntp[blockIdx.x] = sc[0]; }
}

// Pass 2: final reduce -> means
__global__ void k_reduce2() {
    __shared__ float s0[RGRID], s1[RGRID];
    __shared__ int   sc[RGRID];
    int tid = threadIdx.x;
    s0[tid] = g_part0[tid]; s1[tid] = g_part1[tid]; sc[tid] = g_cntp[tid];
    __syncthreads();
    for (int s = RGRID / 2; s > 0; s >>= 1) {
        if (tid < s) { s0[tid] += s0[tid + s]; s1[tid] += s1[tid + s]; sc[tid] += sc[tid + s]; }
        __syncthreads();
    }
    if (tid == 0) {
        float n = (float)(sc[0] > 1 ? sc[0] : 1);
        g_mean0 = s0[0] / n;
        g_mean1 = s1[0] / n;
    }
}

// Main kernel: one thread per ray. Per-thread smem columns for steps + unnormalized cdf.
__global__ void __launch_bounds__(BS) k_main(const float* __restrict__ rd,
                                             const float* __restrict__ cam,
                                             const float* __restrict__ trand,
                                             float* __restrict__ out) {
    __shared__ float steps_s[NSTEP * BS];        // steps[i] at [i*BS+tid]
    __shared__ float cum_s[(NSTEP - 1) * BS];    // unnormalized C[i+1] at [i*BS+tid]

    const int tid = threadIdx.x;
    const int r = blockIdx.x * BS + tid;

    const float cx = cam[0], cy = cam[1], cz = cam[2];
    const float cc = cx * cx + cy * cy + cz * cz;

    const float dx = rd[3 * r + 0], dy = rd[3 * r + 1], dz = rd[3 * r + 2];
    const float dot = dx * cx + dy * cy + dz * cz;
    const float under = dot * dot - (cc - 1.0f);

    float si0, si1;
    if (under > 0.0f) {
        float sq = sqrtf(under);
        si0 = -sq - dot;
        si1 =  sq - dot;
    } else {
        si0 = g_mean0;
        si1 = g_mean1;
    }
    const float min_d = fmaxf(si0, 0.0f);
    const float max_d = fmaxf(si1, 0.0f);
    const float range = max_d - min_d;
    const float sd = range * (1.0f / (float)NSTEP);

    const float inv_s = 20.0855369232f;  // expf(0.3*10)
    const float4* tr4 = reinterpret_cast<const float4*>(trand) + (size_t)r * (NSTEP / 4);
    float* wout = out + (size_t)P_RAYS * 128 + (size_t)r * 63;

    float sig_prev = 0.f;
    float T = 1.0f;
    float cum = 0.0f;

    // Pass 1: steps, sdf, sigmoid chain, alpha/weights, unnormalized cumsum
    #pragma unroll 2
    for (int i4 = 0; i4 < NSTEP / 4; i4++) {
        float4 t4 = tr4[i4];
        #pragma unroll
        for (int ii = 0; ii < 4; ii++) {
            int i = i4 * 4 + ii;
            float t = (ii == 0) ? t4.x : (ii == 1) ? t4.y : (ii == 2) ? t4.z : t4.w;
            float lin = (float)i * (1.0f / (float)(NSTEP - 1));
            float step = fmaf(lin, range, min_d) + (t - 0.5f) * sd;
            steps_s[i * BS + tid] = step;

            // |cam + step*d|^2 with |d|=1:  step^2 + 2*step*dot + cc
            float q = fmaf(step, step + 2.0f * dot, cc);
            q = fmaxf(q, 1e-12f);
            float sdfv = q * rsqrtf(q) - 0.5f;
            float b = __expf(-inv_s * sdfv);
            float sig = __fdividef(1.0f, 1.0f + b);

            if (i > 0) {
                float alpha = (sig_prev - sig + 1e-8f) * __fdividef(1.0f, sig_prev + 1e-8f);
                alpha = fminf(fmaxf(alpha, 0.0f), 1.0f);
                float w = alpha * T;
                T = T * (1.0f - alpha + 1e-7f);
                cum += (w + 1e-8f);
                cum_s[(i - 1) * BS + tid] = cum;
                wout[i - 1] = w;
            }
            sig_prev = sig;
        }
    }

    // Pass 2: importance sampling (scale-free: compare u*W against unnormalized cumsum)
    const float wsum = cum;                       // = C[63] unnormalized
    const float invW = __fdividef(1.0f, wsum);
    const float thr = 1e-8f * wsum;               // denom<1e-8 in normalized space

    float* nsout = out + (size_t)r * 96;
    float* zout  = out + (size_t)P_RAYS * 96 + (size_t)r * 32;

    #pragma unroll
    for (int kb = 0; kb < NIMP / 4; kb++) {
        float zq[4];
        float ns[12];
        #pragma unroll
        for (int kk = 0; kk < 4; kk++) {
            int k = kb * 4 + kk;
            float target = (float)(2 * k + 1) * (1.0f / 64.0f) * wsum;  // u_k * W

            // p = count of cum entries <= target (cum has 63 entries, idx 0..62)
            int p = 0;
            #pragma unroll
            for (int s = 32; s > 0; s >>= 1) {
                int np = p + s;
                if (np <= 63 && cum_s[(np - 1) * BS + tid] <= target) p = np;
            }
            // ind = p+1; below = p, above = min(p+1, 63)
            float cdf_b = (p == 0) ? 0.0f : cum_s[(p - 1) * BS + tid];
            float cdf_a = cum_s[min(p, 62) * BS + tid];
            float bins_b = steps_s[min(p, 63) * BS + tid];
            float bins_a = steps_s[min(p + 1, 63) * BS + tid];
            float dN = cdf_a - cdf_b;
            float tt = (target - cdf_b) * ((dN < thr) ? invW : __fdividef(1.0f, dN));
            float z = fmaf(tt, bins_a - bins_b, bins_b);

            zq[kk] = z;
            ns[kk * 3 + 0] = fmaf(z, dx, cx);
            ns[kk * 3 + 1] = fmaf(z, dy, cy);
            ns[kk * 3 + 2] = fmaf(z, dz, cz);
        }
        *reinterpret_cast<float4*>(zout + kb * 4) = make_float4(zq[0], zq[1], zq[2], zq[3]);
        float4* np4 = reinterpret_cast<float4*>(nsout + kb * 12);
        np4[0] = make_float4(ns[0], ns[1], ns[2],  ns[3]);
        np4[1] = make_float4(ns[4], ns[5], ns[6],  ns[7]);
        np4[2] = make_float4(ns[8], ns[9], ns[10], ns[11]);
    }
}

extern "C" void kernel_launch(void* const* d_in, const int* in_sizes, int n_in,
                              void* d_out, int out_size) {
    const float* rd  = (const float*)d_in[0];
    const float* cam = (const float*)d_in[1];
    const float* tr  = (const float*)d_in[2];
    float* out = (float*)d_out;

    k_reduce1<<<RGRID, RBLK>>>(rd, cam);
    k_reduce2<<<1, RGRID>>>();
    k_main<<<P_RAYS / BS, BS>>>(rd, cam, tr, out);
}

// round 4
// speedup vs baseline: 1.9482x; 1.9482x over previous
#include <cuda_runtime.h>

#define P_RAYS 262144
#define FULLM 0xFFFFFFFFu
#define R1GRID 1024

__device__ float g_part0[R1GRID];
__device__ float g_part1[R1GRID];
__device__ int   g_cntp[R1GRID];
__device__ float g_mean0;
__device__ float g_mean1;

// Pass 1: one ray per thread, 1024 blocks x 256 threads (covers all rays, no loop)
__global__ void __launch_bounds__(256) k_reduce1(const float* __restrict__ rd,
                                                 const float* __restrict__ cam) {
    __shared__ float s0[256], s1[256];
    __shared__ int   sc[256];
    const int tid = threadIdx.x;
    const int r = blockIdx.x * 256 + tid;
    const float cx = cam[0], cy = cam[1], cz = cam[2];
    const float cc = cx * cx + cy * cy + cz * cz;
    const float dx = rd[3 * r + 0], dy = rd[3 * r + 1], dz = rd[3 * r + 2];
    const float dot = dx * cx + dy * cy + dz * cz;
    const float under = dot * dot - (cc - 1.0f);
    float a0 = 0.f, a1 = 0.f; int cnt = 0;
    if (under > 0.0f) {
        float sq = sqrtf(under);
        a0 = -sq - dot; a1 = sq - dot; cnt = 1;
    }
    s0[tid] = a0; s1[tid] = a1; sc[tid] = cnt;
    __syncthreads();
    for (int s = 128; s > 0; s >>= 1) {
        if (tid < s) { s0[tid] += s0[tid + s]; s1[tid] += s1[tid + s]; sc[tid] += sc[tid + s]; }
        __syncthreads();
    }
    if (tid == 0) { g_part0[blockIdx.x] = s0[0]; g_part1[blockIdx.x] = s1[0]; g_cntp[blockIdx.x] = sc[0]; }
}

// Pass 2: final reduce over 1024 partials
__global__ void __launch_bounds__(1024) k_reduce2() {
    __shared__ float s0[R1GRID], s1[R1GRID];
    __shared__ int   sc[R1GRID];
    const int tid = threadIdx.x;
    s0[tid] = g_part0[tid]; s1[tid] = g_part1[tid]; sc[tid] = g_cntp[tid];
    __syncthreads();
    for (int s = R1GRID / 2; s > 0; s >>= 1) {
        if (tid < s) { s0[tid] += s0[tid + s]; s1[tid] += s1[tid + s]; sc[tid] += sc[tid + s]; }
        __syncthreads();
    }
    if (tid == 0) {
        float n = (float)(sc[0] > 1 ? sc[0] : 1);
        g_mean0 = s0[0] / n;
        g_mean1 = s1[0] / n;
    }
}

// Main kernel: ONE WARP PER RAY. Lane l holds steps (2l, 2l+1). No shared memory.
__global__ void __launch_bounds__(256) k_main(const float* __restrict__ rd,
                                              const float* __restrict__ cam,
                                              const float* __restrict__ trand,
                                              float* __restrict__ out) {
    const int lane = threadIdx.x & 31;
    const int r = (blockIdx.x * blockDim.x + threadIdx.x) >> 5;  // ray = global warp id

    const float cx = cam[0], cy = cam[1], cz = cam[2];
    const float cc = cx * cx + cy * cy + cz * cz;

    // Uniform per-warp ray data (all lanes load the same address -> broadcast)
    const float dx = __ldg(rd + 3 * r + 0);
    const float dy = __ldg(rd + 3 * r + 1);
    const float dz = __ldg(rd + 3 * r + 2);
    const float dot = dx * cx + dy * cy + dz * cz;
    const float under = dot * dot - (cc - 1.0f);

    float si0, si1;
    if (under > 0.0f) {
        float sq = sqrtf(under);
        si0 = -sq - dot;
        si1 =  sq - dot;
    } else {
        si0 = g_mean0;
        si1 = g_mean1;
    }
    const float min_d = fmaxf(si0, 0.0f);
    const float max_d = fmaxf(si1, 0.0f);
    const float range = max_d - min_d;
    const float sd = range * (1.0f / 64.0f);

    // ---- per-lane pair of steps ----
    const float2 t2 = reinterpret_cast<const float2*>(trand)[(size_t)r * 32 + lane];
    const int j0 = 2 * lane, j1 = 2 * lane + 1;

    const float inv_s = 20.0855369232f;  // expf(3.0)

    float step0 = fmaf((float)j0 * (1.0f / 63.0f), range, min_d) + (t2.x - 0.5f) * sd;
    float step1 = fmaf((float)j1 * (1.0f / 63.0f), range, min_d) + (t2.y - 0.5f) * sd;

    float q0 = fmaxf(fmaf(step0, step0 + 2.0f * dot, cc), 1e-12f);
    float q1 = fmaxf(fmaf(step1, step1 + 2.0f * dot, cc), 1e-12f);
    float sdf0 = q0 * rsqrtf(q0) - 0.5f;
    float sdf1 = q1 * rsqrtf(q1) - 0.5f;
    float b0 = __expf(-inv_s * sdf0);
    float b1 = __expf(-inv_s * sdf1);
    float sig0 = __fdividef(1.0f, 1.0f + b0);
    float sig1 = __fdividef(1.0f, 1.0f + b1);

    // sig of step 2l+2 lives on lane+1
    float signext = __shfl_down_sync(FULLM, sig0, 1);

    // 1/(sig + 1e-8) approx: (1+b)*(1 - 1e-8*(1+b));  b <= e^10 so err < 5e-8 rel
    float ib0 = 1.0f + b0;
    float ib1 = 1.0f + b1;
    float invse0 = ib0 * (1.0f - 1e-8f * ib0);
    float invse1 = ib1 * (1.0f - 1e-8f * ib1);

    float alpha0 = (sig0 - sig1 + 1e-8f) * invse0;      // alpha[m0], m0 = 2l
    float alpha1 = (sig1 - signext + 1e-8f) * invse1;   // alpha[m1], m1 = 2l+1
    alpha0 = fminf(fmaxf(alpha0, 0.0f), 1.0f);
    alpha1 = fminf(fmaxf(alpha1, 0.0f), 1.0f);
    if (lane == 31) alpha1 = 0.0f;                      // m1=63 is a dummy slot

    // ---- transmittance: exclusive product scan of g = 1-alpha+1e-7 over 64 slots ----
    float g0v = 1.0f - alpha0 + 1e-7f;
    float g1v = 1.0f - alpha1 + 1e-7f;
    float incl = g0v * g1v;
    #pragma unroll
    for (int off = 1; off < 32; off <<= 1) {
        float v = __shfl_up_sync(FULLM, incl, off);
        if (lane >= off) incl *= v;
    }
    float excl = __shfl_up_sync(FULLM, incl, 1);
    if (lane == 0) excl = 1.0f;
    float trans0 = excl;
    float trans1 = excl * g0v;

    float w0 = alpha0 * trans0;
    float w1 = alpha1 * trans1;

    // ---- unnormalized CDF: inclusive sum scan of (w + 1e-8) over 63 slots ----
    float e0 = w0 + 1e-8f;
    float e1 = w1 + 1e-8f;   // lane31's e1 never used downstream of C[62]
    float sinc = e0 + e1;
    #pragma unroll
    for (int off = 1; off < 32; off <<= 1) {
        float v = __shfl_up_sync(FULLM, sinc, off);
        if (lane >= off) sinc += v;
    }
    float sexcl = __shfl_up_sync(FULLM, sinc, 1);
    if (lane == 0) sexcl = 0.0f;
    float c0 = sexcl + e0;        // C[2l]
    float c1 = c0 + e1;           // C[2l+1]

    const float wsum = __shfl_sync(FULLM, c0, 31);   // C[62]
    const float invW = __fdividef(1.0f, wsum);

    // ---- importance sampling: one sample per lane ----
    const float target = (float)(2 * lane + 1) * (1.0f / 64.0f) * wsum;

    int p = 0;
    #pragma unroll
    for (int s = 32; s > 0; s >>= 1) {
        int m = p + s - 1;                 // C index to probe, always <= 62
        float va = __shfl_sync(FULLM, c0, m >> 1);
        float vb = __shfl_sync(FULLM, c1, m >> 1);
        float v = (m & 1) ? vb : va;
        if (v <= target) p += s;
    }
    if (p > 62) p = 62;   // safety (target < wsum implies p <= 62)

    // gather cdf / bins from distributed registers
    int mb = (p == 0) ? 0 : (p - 1);
    float cba = __shfl_sync(FULLM, c0, mb >> 1);
    float cbb = __shfl_sync(FULLM, c1, mb >> 1);
    float cdf_b = (p == 0) ? 0.0f : ((mb & 1) ? cbb : cba);

    float caa = __shfl_sync(FULLM, c0, p >> 1);
    float cab = __shfl_sync(FULLM, c1, p >> 1);
    float cdf_a = (p & 1) ? cab : caa;

    float sba = __shfl_sync(FULLM, step0, p >> 1);
    float sbb = __shfl_sync(FULLM, step1, p >> 1);
    float bins_b = (p & 1) ? sbb : sba;

    int pa = p + 1;                      // <= 63
    float saa = __shfl_sync(FULLM, step0, pa >> 1);
    float sab = __shfl_sync(FULLM, step1, pa >> 1);
    float bins_a = (pa & 1) ? sab : saa;

    float dN = cdf_a - cdf_b;
    float tt = (target - cdf_b) * ((dN < 1e-8f * wsum) ? invW : __fdividef(1.0f, dN));
    float z = fmaf(tt, bins_a - bins_b, bins_b);

    // ---- coalesced outputs ----
    float* zout = out + (size_t)P_RAYS * 96 + (size_t)r * 32;
    zout[lane] = z;

    float* nsout = out + (size_t)r * 96;
    nsout[3 * lane + 0] = fmaf(z, dx, cx);
    nsout[3 * lane + 1] = fmaf(z, dy, cy);
    nsout[3 * lane + 2] = fmaf(z, dz, cz);

    float* wout = out + (size_t)P_RAYS * 128 + (size_t)r * 63;
    wout[j0] = w0;
    if (j1 < 63) wout[j1] = w1;
}

extern "C" void kernel_launch(void* const* d_in, const int* in_sizes, int n_in,
                              void* d_out, int out_size) {
    const float* rd  = (const float*)d_in[0];
    const float* cam = (const float*)d_in[1];
    const float* tr  = (const float*)d_in[2];
    float* out = (float*)d_out;

    k_reduce1<<<R1GRID, 256>>>(rd, cam);
    k_reduce2<<<1, R1GRID>>>();
    k_main<<<(P_RAYS * 32) / 256, 256>>>(rd, cam, tr, out);
}